// round 2
// baseline (speedup 1.0000x reference)
#include <cuda_runtime.h>
#include <math_constants.h>

#define NSEQ    8
#define QLEN    128
#define NQH     32
#define NKVH    8
#define GQA     4
#define HD      128
#define BLKSZ   16
#define MAXBLK  128
#define LTOT    (MAXBLK*BLKSZ)
#define NSEG    4
#define TILEC   32

#define LT        64
#define NTHREADS  512

#define QST_STRIDE 132
#define KS_STRIDE  64
#define VT_STRIDE  136
#define PT_STRIDE  132

#define SMEM_FLOATS (HD*QST_STRIDE + HD*KS_STRIDE + LT*VT_STRIDE + LT*PT_STRIDE)
#define SMEM_BYTES  (SMEM_FLOATS*4)

typedef unsigned long long ull;

__device__ __forceinline__ ull pack2(float lo, float hi) {
    ull r;
    asm("mov.b64 %0, {%1, %2};" : "=l"(r) : "f"(lo), "f"(hi));
    return r;
}
__device__ __forceinline__ void fma2(ull& d, ull a, ull b) {
    asm("fma.rn.f32x2 %0, %1, %2, %0;" : "+l"(d) : "l"(a), "l"(b));
}
__device__ __forceinline__ void mul2(ull& d, ull a) {
    asm("mul.rn.f32x2 %0, %0, %1;" : "+l"(d) : "l"(a));
}
__device__ __forceinline__ void unpack2(float& lo, float& hi, ull v) {
    asm("mov.b64 {%0, %1}, %2;" : "=f"(lo), "=f"(hi) : "l"(v));
}

__global__ void __launch_bounds__(NTHREADS, 1)
paged_seg_attn_kernel(const float* __restrict__ q,
                      const float* __restrict__ kc,
                      const float* __restrict__ vc,
                      const int*   __restrict__ bt,
                      const int*   __restrict__ seqlens,
                      const float* __restrict__ scale_p,
                      const float* __restrict__ softcap_p,
                      float*       __restrict__ out)
{
    extern __shared__ float sm[];
    float* Qst = sm;
    float* Ks  = Qst + HD*QST_STRIDE;
    float* Vt  = Ks  + HD*KS_STRIDE;
    float* Pt  = Vt  + LT*VT_STRIDE;

    const int seg = blockIdx.x;
    const int g   = blockIdx.y;
    const int z   = blockIdx.z;
    const int s   = z >> 3;
    const int kv  = z & 7;
    const int h   = kv*GQA + g;
    const int tid = threadIdx.x;

    const float scale  = *scale_p;
    const float cap    = *softcap_p;
    const float invcap = (cap > 0.f) ? (1.0f/cap) : 0.f;

    const int seq_len = seqlens[s];
    const int ctx     = seq_len - QLEN;
    const int span    = ((seq_len + NSEG*TILEC - 1)/(NSEG*TILEC))*TILEC;
    const int seg_start = seg*span;
    const int seg_end   = min(seg_start + span, LTOT);

    const int* btrow = bt + s*MAXBLK;

    // ---- load Q tile transposed: Qst[d][q] ----
    {
        const float* qbase = q + (size_t)s*QLEN*NQH*HD + (size_t)h*HD;
        #pragma unroll
        for (int it = 0; it < 8; it++) {
            int i  = tid + it*NTHREADS;
            int qi = i & 127;
            int d0 = (i >> 7) * 4;
            float4 v = *(const float4*)(qbase + (size_t)qi*(NQH*HD) + d0);
            Qst[(d0+0)*QST_STRIDE + qi] = v.x;
            Qst[(d0+1)*QST_STRIDE + qi] = v.y;
            Qst[(d0+2)*QST_STRIDE + qi] = v.z;
            Qst[(d0+3)*QST_STRIDE + qi] = v.w;
        }
    }

    const int qg  = tid >> 4;    // 0..31
    const int lg  = tid & 15;    // 0..15
    const int qg4 = qg * 4;
    const int lg4 = lg * 4;
    const int dg8 = lg * 8;

    ull acc[4][4];
    #pragma unroll
    for (int a = 0; a < 4; a++)
        #pragma unroll
        for (int b = 0; b < 4; b++) acc[a][b] = 0ULL;

    float mrun[4];
    #pragma unroll
    for (int a = 0; a < 4; a++) mrun[a] = -CUDART_INF_F;

    for (int base = seg_start; base < seg_end; base += LT) {
        __syncthreads();

        // K chunk: Ks[d][l]
        #pragma unroll
        for (int it = 0; it < 4; it++) {
            int i   = tid + it*NTHREADS;
            int d   = i >> 4;
            int r   = i & 15;
            int blk = r >> 2;
            int bq  = (r & 3) * 4;
            int kb  = min((base >> 4) + blk, MAXBLK-1);
            int pb  = btrow[kb];
            float4 v = *(const float4*)(kc + (((size_t)pb*NKVH + kv)*HD + d)*BLKSZ + bq);
            *(float4*)(Ks + d*KS_STRIDE + blk*BLKSZ + bq) = v;
        }
        // V chunk transposed: Vt[l][d]
        #pragma unroll
        for (int it = 0; it < 4; it++) {
            int i   = tid + it*NTHREADS;
            int d   = i & 127;
            int rr  = i >> 7;
            int blk = rr >> 2;
            int bq  = (rr & 3) * 4;
            int kb  = min((base >> 4) + blk, MAXBLK-1);
            int pb  = btrow[kb];
            float4 v = *(const float4*)(vc + (((size_t)pb*NKVH + kv)*HD + d)*BLKSZ + bq);
            int l0 = blk*BLKSZ + bq;
            Vt[(l0+0)*VT_STRIDE + d] = v.x;
            Vt[(l0+1)*VT_STRIDE + d] = v.y;
            Vt[(l0+2)*VT_STRIDE + d] = v.z;
            Vt[(l0+3)*VT_STRIDE + d] = v.w;
        }
        __syncthreads();

        // ---- QK ----
        ull sc2[2][4];
        #pragma unroll
        for (int a = 0; a < 2; a++)
            #pragma unroll
            for (int b = 0; b < 4; b++) sc2[a][b] = 0ULL;

        #pragma unroll 8
        for (int d = 0; d < HD; d++) {
            ulonglong2 qv = *(const ulonglong2*)(Qst + d*QST_STRIDE + qg4);
            float4 kf = *(const float4*)(Ks + d*KS_STRIDE + lg4);
            ull k0 = pack2(kf.x, kf.x);
            ull k1 = pack2(kf.y, kf.y);
            ull k2 = pack2(kf.z, kf.z);
            ull k3 = pack2(kf.w, kf.w);
            fma2(sc2[0][0], qv.x, k0); fma2(sc2[1][0], qv.y, k0);
            fma2(sc2[0][1], qv.x, k1); fma2(sc2[1][1], qv.y, k1);
            fma2(sc2[0][2], qv.x, k2); fma2(sc2[1][2], qv.y, k2);
            fma2(sc2[0][3], qv.x, k3); fma2(sc2[1][3], qv.y, k3);
        }

        float sv[4][4];
        #pragma unroll
        for (int qp = 0; qp < 2; qp++)
            #pragma unroll
            for (int lc = 0; lc < 4; lc++) {
                float lo, hi;
                unpack2(lo, hi, sc2[qp][lc]);
                sv[2*qp+0][lc] = lo;
                sv[2*qp+1][lc] = hi;
            }

        // scale + softcap + mask; per-row max
        float rmax[4];
        #pragma unroll
        for (int qi = 0; qi < 4; qi++) {
            int qrow = qg4 + qi;
            int kmax = ctx + qrow;
            float rm = -CUDART_INF_F;
            #pragma unroll
            for (int lc = 0; lc < 4; lc++) {
                int kpos = base + lg4 + lc;
                float v = sv[qi][lc] * scale;
                if (cap > 0.f) {
                    float e = __expf(2.f * v * invcap);
                    v = cap * __fdividef(e - 1.f, e + 1.f);
                }
                bool ok = (kpos <= kmax) && (kpos < seg_end);
                v = ok ? v : -CUDART_INF_F;
                sv[qi][lc] = v;
                rm = fmaxf(rm, v);
            }
            rmax[qi] = rm;
        }
        #pragma unroll
        for (int off = 1; off < 16; off <<= 1) {
            #pragma unroll
            for (int qi = 0; qi < 4; qi++)
                rmax[qi] = fmaxf(rmax[qi], __shfl_xor_sync(0xffffffffu, rmax[qi], off));
        }

        // online max + rescale + exp
        #pragma unroll
        for (int qi = 0; qi < 4; qi++) {
            float mnew = fmaxf(mrun[qi], rmax[qi]);
            float corr = (mnew == -CUDART_INF_F) ? 1.f : __expf(mrun[qi] - mnew);
            mrun[qi] = mnew;
            ull c2 = pack2(corr, corr);
            #pragma unroll
            for (int dp = 0; dp < 4; dp++) mul2(acc[qi][dp], c2);
            #pragma unroll
            for (int lc = 0; lc < 4; lc++) {
                float srow = sv[qi][lc];
                sv[qi][lc] = (srow == -CUDART_INF_F) ? 0.f : __expf(srow - mnew);
            }
        }

        // Pt[l][q]
        #pragma unroll
        for (int lc = 0; lc < 4; lc++) {
            float4 pv = make_float4(sv[0][lc], sv[1][lc], sv[2][lc], sv[3][lc]);
            *(float4*)(Pt + (lg4+lc)*PT_STRIDE + qg4) = pv;
        }
        __syncthreads();

        // ---- PV ----
        #pragma unroll 4
        for (int l = 0; l < LT; l++) {
            float4 pf = *(const float4*)(Pt + l*PT_STRIDE + qg4);
            ulonglong2 va = *(const ulonglong2*)(Vt + l*VT_STRIDE + dg8);
            ulonglong2 vb = *(const ulonglong2*)(Vt + l*VT_STRIDE + dg8+4);
            ull p0 = pack2(pf.x, pf.x);
            ull p1 = pack2(pf.y, pf.y);
            ull p2 = pack2(pf.z, pf.z);
            ull p3 = pack2(pf.w, pf.w);
            fma2(acc[0][0], p0, va.x); fma2(acc[0][1], p0, va.y);
            fma2(acc[0][2], p0, vb.x); fma2(acc[0][3], p0, vb.y);
            fma2(acc[1][0], p1, va.x); fma2(acc[1][1], p1, va.y);
            fma2(acc[1][2], p1, vb.x); fma2(acc[1][3], p1, vb.y);
            fma2(acc[2][0], p2, va.x); fma2(acc[2][1], p2, va.y);
            fma2(acc[2][2], p2, vb.x); fma2(acc[2][3], p2, vb.y);
            fma2(acc[3][0], p3, va.x); fma2(acc[3][1], p3, va.y);
            fma2(acc[3][2], p3, vb.x); fma2(acc[3][3], p3, vb.y);
        }
    }

    // ---- write out[t][h][seg][d] ----
    #pragma unroll
    for (int qi = 0; qi < 4; qi++) {
        int qrow = qg4 + qi;
        size_t o = ((((size_t)(s*QLEN + qrow))*NQH + h)*NSEG + seg)*(size_t)HD + dg8;
        ulonglong2 w0; w0.x = acc[qi][0]; w0.y = acc[qi][1];
        ulonglong2 w1; w1.x = acc[qi][2]; w1.y = acc[qi][3];
        *(ulonglong2*)(out + o)     = w0;
        *(ulonglong2*)(out + o + 4) = w1;
    }
}

extern "C" void kernel_launch(void* const* d_in, const int* in_sizes, int n_in,
                              void* d_out, int out_size) {
    const float* q   = (const float*)d_in[0];
    const float* kc  = (const float*)d_in[1];
    const float* vc  = (const float*)d_in[2];
    const int*   bt  = (const int*)d_in[3];
    const int*   sl  = (const int*)d_in[4];
    // d_in[5] = query_start_len (unused)
    const float* sc  = (const float*)d_in[6];
    // d_in[7]=k_scale, d_in[8]=v_scale (no-ops for fp32 cache)
    const float* cap = (const float*)d_in[9];
    float* out = (float*)d_out;

    static int smem_set = 0;
    if (!smem_set) {
        cudaFuncSetAttribute(paged_seg_attn_kernel,
                             cudaFuncAttributeMaxDynamicSharedMemorySize, SMEM_BYTES);
        smem_set = 1;
    }
    dim3 grid(NSEG, GQA, NSEQ*NKVH);
    paged_seg_attn_kernel<<<grid, NTHREADS, SMEM_BYTES>>>(q, kc, vc, bt, sl, sc, cap, out);
}

// round 3
// speedup vs baseline: 1.2755x; 1.2755x over previous
#include <cuda_runtime.h>
#include <math_constants.h>

#define NSEQ    8
#define QLEN    128
#define NQH     32
#define NKVH    8
#define GQA     4
#define HD      128
#define BLKSZ   16
#define MAXBLK  128
#define LTOT    2048
#define NSEG    4
#define TILEC   32

#define LT        128       // keys per chunk (8 physical blocks)
#define NTHREADS  256

#define QST 132             // Qst[d][q]
#define KST 132             // Ks[d][l]  (reused as Pt[l][q])
#define VST 132             // Vt[l][d]

#define SMEM_FLOATS (HD*QST + HD*KST + LT*VST)
#define SMEM_BYTES  (SMEM_FLOATS*4)

typedef unsigned long long ull;

__device__ __forceinline__ ull pack2(float lo, float hi) {
    ull r;
    asm("mov.b64 %0, {%1, %2};" : "=l"(r) : "f"(lo), "f"(hi));
    return r;
}
__device__ __forceinline__ void fma2(ull& d, ull a, ull b) {
    asm("fma.rn.f32x2 %0, %1, %2, %0;" : "+l"(d) : "l"(a), "l"(b));
}
__device__ __forceinline__ void mul2(ull& d, ull a) {
    asm("mul.rn.f32x2 %0, %0, %1;" : "+l"(d) : "l"(a), "l"(a));
}
__device__ __forceinline__ void unpack2(float& lo, float& hi, ull v) {
    asm("mov.b64 {%0, %1}, %2;" : "=f"(lo), "=f"(hi) : "l"(v));
}

__global__ void __launch_bounds__(NTHREADS, 1)
paged_seg_attn_kernel(const float* __restrict__ q,
                      const float* __restrict__ kc,
                      const float* __restrict__ vc,
                      const int*   __restrict__ bt,
                      const int*   __restrict__ seqlens,
                      const float* __restrict__ scale_p,
                      const float* __restrict__ softcap_p,
                      float*       __restrict__ out)
{
    extern __shared__ float sm[];
    float* Qst = sm;                    // [128][132]  Q transposed [d][q]
    float* Ks  = sm + HD*QST;           // [128][132]  K [d][l]; later Pt [l][q]
    float* Vt  = Ks + HD*KST;           // [128][132]  V transposed [l][d]

    const int seg = blockIdx.x;
    const int g   = blockIdx.y;
    const int z   = blockIdx.z;
    const int s   = z >> 3;
    const int kv  = z & 7;
    const int h   = kv*GQA + g;
    const int tid = threadIdx.x;

    const float scale = *scale_p;
    const float cap   = *softcap_p;
    const bool  docap = (cap > 0.f);
    const float tcoef = docap ? (2.0f*scale/cap) : 0.f;

    const int seq_len = seqlens[s];
    const int ctx     = seq_len - QLEN;
    const int span    = ((seq_len + NSEG*TILEC - 1)/(NSEG*TILEC))*TILEC;
    const int seg_start = seg*span;
    const int seg_end   = min(seg_start + span, LTOT);

    const int* btrow = bt + s*MAXBLK;

    // ---- load Q tile transposed: Qst[d][q] ----
    {
        const float* qbase = q + (size_t)s*QLEN*NQH*HD + (size_t)h*HD;
        #pragma unroll
        for (int it = 0; it < 16; it++) {
            int i  = tid + it*NTHREADS;      // 0..4095
            int qi = i & 127;
            int d0 = (i >> 7) * 4;
            float4 v = *(const float4*)(qbase + (size_t)qi*(NQH*HD) + d0);
            Qst[(d0+0)*QST + qi] = v.x;
            Qst[(d0+1)*QST + qi] = v.y;
            Qst[(d0+2)*QST + qi] = v.z;
            Qst[(d0+3)*QST + qi] = v.w;
        }
    }

    const int qg  = tid >> 4;     // 0..15 -> q rows qg*8..+7
    const int lg  = tid & 15;     // 0..15 -> l cols {4lg..+3, 64+4lg..+3}; PV: d cols same split
    const int qg8 = qg * 8;
    const int lg4 = lg * 4;

    ull acc[8][4];                // [q][d-pair]; d pairs: (4lg,4lg+1),(4lg+2,4lg+3),(64+4lg,+1),(+2,+3)
    #pragma unroll
    for (int a = 0; a < 8; a++)
        #pragma unroll
        for (int b = 0; b < 4; b++) acc[a][b] = 0ULL;

    float mrun[8];
    #pragma unroll
    for (int a = 0; a < 8; a++) mrun[a] = -CUDART_INF_F;

    for (int base = seg_start; base < seg_end; base += LT) {
        __syncthreads();   // previous PV done (Ks/Pt and Vt free to overwrite)

        // ---- load K chunk: Ks[d][l] (gmem-coalesced: lanes sweep tokens) ----
        #pragma unroll
        for (int it = 0; it < 16; it++) {
            int i   = tid + it*NTHREADS;    // 0..4095
            int d   = i >> 5;               // 0..127
            int r   = i & 31;
            int blk = r >> 2;               // 0..7
            int t4  = (r & 3) * 4;
            int pb  = btrow[(base >> 4) + blk];
            float4 v = *(const float4*)(kc + (((size_t)pb*NKVH + kv)*HD + d)*BLKSZ + t4);
            *(float4*)(Ks + d*KST + blk*BLKSZ + t4) = v;
        }
        // ---- load V chunk transposed: Vt[l][d] (lanes sweep d -> conflict-free stores) ----
        #pragma unroll
        for (int it = 0; it < 16; it++) {
            int i   = tid + it*NTHREADS;
            int d   = i & 127;
            int rr  = i >> 7;               // 0..31
            int blk = rr >> 2;
            int t4  = (rr & 3) * 4;
            int pb  = btrow[(base >> 4) + blk];
            float4 v = *(const float4*)(vc + (((size_t)pb*NKVH + kv)*HD + d)*BLKSZ + t4);
            int l0 = blk*BLKSZ + t4;
            Vt[(l0+0)*VST + d] = v.x;
            Vt[(l0+1)*VST + d] = v.y;
            Vt[(l0+2)*VST + d] = v.z;
            Vt[(l0+3)*VST + d] = v.w;
        }
        __syncthreads();

        // ---- QK: 8q x 8l per thread, packed along q-pairs ----
        ull sc2[4][8];
        #pragma unroll
        for (int a = 0; a < 4; a++)
            #pragma unroll
            for (int b = 0; b < 8; b++) sc2[a][b] = 0ULL;

        #pragma unroll 2
        for (int d = 0; d < HD; d++) {
            const float* qrow = Qst + d*QST + qg8;
            ulonglong2 qa = *(const ulonglong2*)(qrow);      // q pairs 0,1
            ulonglong2 qb = *(const ulonglong2*)(qrow + 4);  // q pairs 2,3
            float4 k0 = *(const float4*)(Ks + d*KST + lg4);
            float4 k1 = *(const float4*)(Ks + d*KST + 64 + lg4);
            ull kk0 = pack2(k0.x, k0.x), kk1 = pack2(k0.y, k0.y);
            ull kk2 = pack2(k0.z, k0.z), kk3 = pack2(k0.w, k0.w);
            ull kk4 = pack2(k1.x, k1.x), kk5 = pack2(k1.y, k1.y);
            ull kk6 = pack2(k1.z, k1.z), kk7 = pack2(k1.w, k1.w);
            fma2(sc2[0][0], qa.x, kk0); fma2(sc2[1][0], qa.y, kk0);
            fma2(sc2[2][0], qb.x, kk0); fma2(sc2[3][0], qb.y, kk0);
            fma2(sc2[0][1], qa.x, kk1); fma2(sc2[1][1], qa.y, kk1);
            fma2(sc2[2][1], qb.x, kk1); fma2(sc2[3][1], qb.y, kk1);
            fma2(sc2[0][2], qa.x, kk2); fma2(sc2[1][2], qa.y, kk2);
            fma2(sc2[2][2], qb.x, kk2); fma2(sc2[3][2], qb.y, kk2);
            fma2(sc2[0][3], qa.x, kk3); fma2(sc2[1][3], qa.y, kk3);
            fma2(sc2[2][3], qb.x, kk3); fma2(sc2[3][3], qb.y, kk3);
            fma2(sc2[0][4], qa.x, kk4); fma2(sc2[1][4], qa.y, kk4);
            fma2(sc2[2][4], qb.x, kk4); fma2(sc2[3][4], qb.y, kk4);
            fma2(sc2[0][5], qa.x, kk5); fma2(sc2[1][5], qa.y, kk5);
            fma2(sc2[2][5], qb.x, kk5); fma2(sc2[3][5], qb.y, kk5);
            fma2(sc2[0][6], qa.x, kk6); fma2(sc2[1][6], qa.y, kk6);
            fma2(sc2[2][6], qb.x, kk6); fma2(sc2[3][6], qb.y, kk6);
            fma2(sc2[0][7], qa.x, kk7); fma2(sc2[1][7], qa.y, kk7);
            fma2(sc2[2][7], qb.x, kk7); fma2(sc2[3][7], qb.y, kk7);
        }

        // unpack to sv[8 q][8 l]
        float sv[8][8];
        #pragma unroll
        for (int qp = 0; qp < 4; qp++)
            #pragma unroll
            for (int lc = 0; lc < 8; lc++) {
                float lo, hi;
                unpack2(lo, hi, sc2[qp][lc]);
                sv[2*qp+0][lc] = lo;
                sv[2*qp+1][lc] = hi;
            }

        // ---- scale + softcap + causal/segment mask; per-row max ----
        float rmax[8];
        #pragma unroll
        for (int qi = 0; qi < 8; qi++) {
            int kmax = ctx + qg8 + qi;
            float rm = -CUDART_INF_F;
            #pragma unroll
            for (int lc = 0; lc < 8; lc++) {
                int lphys = (lc < 4) ? (lg4 + lc) : (64 + lg4 + lc - 4);
                int kpos  = base + lphys;
                float raw = sv[qi][lc];
                float v;
                if (docap) {
                    float e = __expf(raw * tcoef);       // e^{2*scale*raw/cap}
                    v = __fdividef(cap*(e - 1.f), e + 1.f);
                } else {
                    v = raw * scale;
                }
                bool ok = (kpos <= kmax) && (kpos < seg_end);
                v = ok ? v : -CUDART_INF_F;
                sv[qi][lc] = v;
                rm = fmaxf(rm, v);
            }
            rmax[qi] = rm;
        }
        // reduce across the 16 lanes sharing this qg (lanes stay within 16-lane halves)
        #pragma unroll
        for (int off = 1; off < 16; off <<= 1) {
            #pragma unroll
            for (int qi = 0; qi < 8; qi++)
                rmax[qi] = fmaxf(rmax[qi], __shfl_xor_sync(0xffffffffu, rmax[qi], off));
        }

        // ---- online max update + acc rescale + p = exp(s - m) ----
        #pragma unroll
        for (int qi = 0; qi < 8; qi++) {
            float mnew = fmaxf(mrun[qi], rmax[qi]);
            float corr = (mnew == -CUDART_INF_F) ? 1.f : __expf(mrun[qi] - mnew);
            mrun[qi] = mnew;
            ull c2 = pack2(corr, corr);
            #pragma unroll
            for (int dp = 0; dp < 4; dp++) mul2(acc[qi][dp], c2);
            #pragma unroll
            for (int lc = 0; lc < 8; lc++) {
                float srow = sv[qi][lc];
                sv[qi][lc] = (srow == -CUDART_INF_F) ? 0.f : __expf(srow - mnew);
            }
        }

        __syncthreads();   // everyone done reading Ks -> safe to overwrite with Pt

        // ---- store P transposed into Ks buffer: Pt[l][q], XOR-swizzled columns ----
        #pragma unroll
        for (int lc = 0; lc < 8; lc++) {
            int row = (lc < 4) ? (lg4 + lc) : (64 + lg4 + lc - 4);
            int swz = ((row >> 2) & 7) << 1;
            int c0  = (qg*2)     ^ swz;
            int c1  = (qg*2 + 1) ^ swz;
            float4 a = make_float4(sv[0][lc], sv[1][lc], sv[2][lc], sv[3][lc]);
            float4 b = make_float4(sv[4][lc], sv[5][lc], sv[6][lc], sv[7][lc]);
            *(float4*)(Ks + row*KST + c0*4) = a;
            *(float4*)(Ks + row*KST + c1*4) = b;
        }
        __syncthreads();

        // ---- PV: 8q x 8d per thread, packed along d-pairs ----
        #pragma unroll 2
        for (int l = 0; l < LT; l++) {
            int swz = ((l >> 2) & 7) << 1;
            const float* prow = Ks + l*KST;
            float4 p0 = *(const float4*)(prow + (((qg*2)    ^ swz) * 4));
            float4 p1 = *(const float4*)(prow + (((qg*2 + 1)^ swz) * 4));
            ulonglong2 va = *(const ulonglong2*)(Vt + l*VST + lg4);
            ulonglong2 vb = *(const ulonglong2*)(Vt + l*VST + 64 + lg4);
            ull pp0 = pack2(p0.x, p0.x), pp1 = pack2(p0.y, p0.y);
            ull pp2 = pack2(p0.z, p0.z), pp3 = pack2(p0.w, p0.w);
            ull pp4 = pack2(p1.x, p1.x), pp5 = pack2(p1.y, p1.y);
            ull pp6 = pack2(p1.z, p1.z), pp7 = pack2(p1.w, p1.w);
            fma2(acc[0][0], pp0, va.x); fma2(acc[0][1], pp0, va.y);
            fma2(acc[0][2], pp0, vb.x); fma2(acc[0][3], pp0, vb.y);
            fma2(acc[1][0], pp1, va.x); fma2(acc[1][1], pp1, va.y);
            fma2(acc[1][2], pp1, vb.x); fma2(acc[1][3], pp1, vb.y);
            fma2(acc[2][0], pp2, va.x); fma2(acc[2][1], pp2, va.y);
            fma2(acc[2][2], pp2, vb.x); fma2(acc[2][3], pp2, vb.y);
            fma2(acc[3][0], pp3, va.x); fma2(acc[3][1], pp3, va.y);
            fma2(acc[3][2], pp3, vb.x); fma2(acc[3][3], pp3, vb.y);
            fma2(acc[4][0], pp4, va.x); fma2(acc[4][1], pp4, va.y);
            fma2(acc[4][2], pp4, vb.x); fma2(acc[4][3], pp4, vb.y);
            fma2(acc[5][0], pp5, va.x); fma2(acc[5][1], pp5, va.y);
            fma2(acc[5][2], pp5, vb.x); fma2(acc[5][3], pp5, vb.y);
            fma2(acc[6][0], pp6, va.x); fma2(acc[6][1], pp6, va.y);
            fma2(acc[6][2], pp6, vb.x); fma2(acc[6][3], pp6, vb.y);
            fma2(acc[7][0], pp7, va.x); fma2(acc[7][1], pp7, va.y);
            fma2(acc[7][2], pp7, vb.x); fma2(acc[7][3], pp7, vb.y);
        }
    }

    // ---- write out[t][h][seg][d] ----
    #pragma unroll
    for (int qi = 0; qi < 8; qi++) {
        int qrow = qg8 + qi;
        size_t o = ((((size_t)(s*QLEN + qrow))*NQH + h)*NSEG + seg)*(size_t)HD;
        ulonglong2 w0; w0.x = acc[qi][0]; w0.y = acc[qi][1];
        ulonglong2 w1; w1.x = acc[qi][2]; w1.y = acc[qi][3];
        *(ulonglong2*)(out + o + lg4)      = w0;
        *(ulonglong2*)(out + o + 64 + lg4) = w1;
    }
}

extern "C" void kernel_launch(void* const* d_in, const int* in_sizes, int n_in,
                              void* d_out, int out_size) {
    const float* q   = (const float*)d_in[0];
    const float* kc  = (const float*)d_in[1];
    const float* vc  = (const float*)d_in[2];
    const int*   bt  = (const int*)d_in[3];
    const int*   sl  = (const int*)d_in[4];
    const float* sc  = (const float*)d_in[6];
    const float* cap = (const float*)d_in[9];
    float* out = (float*)d_out;

    static int smem_set = 0;
    if (!smem_set) {
        cudaFuncSetAttribute(paged_seg_attn_kernel,
                             cudaFuncAttributeMaxDynamicSharedMemorySize, SMEM_BYTES);
        smem_set = 1;
    }
    dim3 grid(NSEG, GQA, NSEQ*NKVH);
    paged_seg_attn_kernel<<<grid, NTHREADS, SMEM_BYTES>>>(q, kc, vc, bt, sl, sc, cap, out);
}